// round 12
// baseline (speedup 1.0000x reference)
#include <cuda_runtime.h>
#include <cuda_fp16.h>
#include <cuda_pipeline.h>
#include <cstdint>
#include <cstddef>

#define CDIM   256
#define KCODES 1024
#define HW     1024
#define NVEC   32768
#define QELEMS (NVEC * CDIM)

#define ESCALE 2048.0f          // 2^11, exact scaling of E before fp16 round
#define EINV   (1.0f / 2048.0f)

#define FIXCAP  8192
#define FIXBCAP 512
#define WIN_ULP 8.0f            // flag window: 8 d-grid cells (>30 sigma of hh-only error)

// ---- dynamic smem layout (bytes) ----
#define SA_H   0                // A-high: 128 rows x 512B (256 fp16), swizzled
#define SB     65536            // 2 buffers x 16KB (Bh only)
#define SNE    98304            // 1024 floats
#define SB1    102400           // float[128][2]
#define SB2    103424
#define SB3    104448
#define SI1    105472
#define SI2    106496
#define SROW   107520           // int[128]
#define SRED   108032           // float[8]
#define SMEM_TOTAL 108544

__device__ float  g_ne[KCODES];
__device__ float  g_nz[NVEC];
__device__ double g_loss;
__device__ int    g_cntA, g_cntB;
__device__ int    g_fixA_row[FIXCAP], g_fixA_c1[FIXCAP], g_fixA_c2[FIXCAP];
__device__ int    g_fixB_row[FIXBCAP];
__device__ int    g_code[NVEC];
// E high-split (scaled by 2^11), [code][k] fp16, 512B rows, XOR-swizzled 16B chunks
__device__ __align__(16) __half g_Bh[KCODES * CDIM];
// z high-split, same swizzled row layout (LDSM-ready), 16MB
__device__ __align__(16) __half g_Ah[NVEC * CDIM];

__device__ __forceinline__ uint32_t smem_u32(const void* p) {
    uint32_t a;
    asm("{ .reg .u64 t; cvta.to.shared.u64 t, %1; cvt.u32.u64 %0, t; }" : "=r"(a) : "l"(p));
    return a;
}
__device__ __forceinline__ float ulpf(float v) {
    return __int_as_float(__float_as_int(v) & 0x7f800000) * 1.1920929e-07f;
}

#define LDSM4(r, addr) \
    asm volatile("ldmatrix.sync.aligned.m8n8.x4.shared.b16 {%0,%1,%2,%3}, [%4];" \
        : "=r"((r)[0]), "=r"((r)[1]), "=r"((r)[2]), "=r"((r)[3]) : "r"(addr))

#define MMA16816(acc, a, b0, b1) \
    asm volatile("mma.sync.aligned.m16n8k16.row.col.f32.f16.f16.f32 " \
        "{%0,%1,%2,%3}, {%4,%5,%6,%7}, {%8,%9}, {%0,%1,%2,%3};" \
        : "+f"((acc)[0]), "+f"((acc)[1]), "+f"((acc)[2]), "+f"((acc)[3]) \
        : "r"((a)[0]), "r"((a)[1]), "r"((a)[2]), "r"((a)[3]), "r"(b0), "r"(b1))

__device__ __forceinline__ uint32_t pack2h(float x0, float x1) {
    return (uint32_t)__half_as_ushort(__float2half_rn(x0)) |
           ((uint32_t)__half_as_ushort(__float2half_rn(x1)) << 16);
}

// merge two sorted (b1,i1,b2,i2,b3) triples, lexicographic (d, idx) order
__device__ __forceinline__ void merge3c(float& b1, int& i1, float& b2, int& i2, float& b3,
                                        float ob1, int oi1, float ob2, int oi2, float ob3) {
    float mb1 = b1, mb2 = b2, mb3 = b3;
    int   mi1 = i1, mi2 = i2;
    if (ob1 < mb1 || (ob1 == mb1 && oi1 < mi1)) {
        b1 = ob1; i1 = oi1;
        if (mb1 < ob2 || (mb1 == ob2 && mi1 < oi2)) {
            b2 = mb1; i2 = mi1; b3 = fminf(ob2, mb2);
        } else {
            b2 = ob2; i2 = oi2; b3 = fminf(ob3, mb1);
        }
    } else {
        if (ob1 < mb2 || (ob1 == mb2 && oi1 < mi2)) {
            b2 = ob1; i2 = oi1; b3 = fminf(mb2, ob2);
        } else {
            b3 = fminf(mb3, ob1);
        }
    }
}

// ======== prep: E norms (unscaled) + scaled fp16 high-split, swizzled ========
__global__ void vq_prep_e(const float* __restrict__ E) {
    int code = blockIdx.x, t = threadIdx.x;            // 64 threads, 4 k each
    float4 v = ((const float4*)(E + (size_t)code * CDIM))[t];
    float s = v.x * v.x + v.y * v.y + v.z * v.z + v.w * v.w;

    uint32_t h01 = pack2h(v.x * ESCALE, v.y * ESCALE);
    uint32_t h23 = pack2h(v.z * ESCALE, v.w * ESCALE);

    int k0 = t * 4;
    int g  = k0 >> 3;
    uint32_t off = (uint32_t)code * 512 +
                   ((uint32_t)(g ^ (code & 7)) << 4) + (((uint32_t)k0 & 7) << 1);
    *(uint2*)((char*)g_Bh + off) = make_uint2(h01, h23);

    for (int o = 16; o > 0; o >>= 1) s += __shfl_down_sync(0xffffffffu, s, o);
    __shared__ float red[2];
    if ((t & 31) == 0) red[t >> 5] = s;
    __syncthreads();
    if (t == 0) g_ne[code] = red[0] + red[1];
}

// ======== prep: ||z||^2 (ascending-k FMA, bit-identical to before) + z fp16 split ========
__global__ void vq_prep_z(const float* __restrict__ Z) {
    int v = blockIdx.x * 128 + threadIdx.x;
    if (v == 0) { g_loss = 0.0; g_cntA = 0; g_cntB = 0; }
    int img = v >> 10, hw = v & 1023;
    const float* zp = Z + (size_t)img * CDIM * HW + hw;
    uint32_t base = (uint32_t)v * 512;
    uint32_t rx   = ((uint32_t)v & 7) << 4;
    float nz = 0.f;
#pragma unroll 4
    for (int g = 0; g < 32; g++) {
        float x[8];
#pragma unroll
        for (int i = 0; i < 8; i++) x[i] = zp[(size_t)(g * 8 + i) * HW];
#pragma unroll
        for (int i = 0; i < 8; i++) nz = fmaf(x[i], x[i], nz);
        uint4 h;
        h.x = pack2h(x[0], x[1]); h.y = pack2h(x[2], x[3]);
        h.z = pack2h(x[4], x[5]); h.w = pack2h(x[6], x[7]);
        *(uint4*)((char*)g_Ah + base + ((((uint32_t)g) << 4) ^ rx)) = h;
    }
    g_nz[v] = nz;
}

// ======== main: mma.sync hh-pass GEMM + top-3 argmin + gather, occ 2 ========
__global__ __launch_bounds__(256, 2)
void vq_main(const float* __restrict__ Z, const float* __restrict__ E,
             float* __restrict__ out) {
    extern __shared__ __align__(16) char smem[];
    const uint32_t sb = smem_u32(smem);
    const int tid = threadIdx.x, lane = tid & 31, wid = tid >> 5;
    const int wm = wid & 3, wn = wid >> 2;              // 4m x 2n warp grid
    float* nes = (float*)(smem + SNE);

    for (int i = tid; i < KCODES; i += 256) nes[i] = g_ne[i];

    const int arow0 = wm * 32 + (lane & 7) + ((lane >> 3) & 1) * 8;
    const uint32_t arx  = ((uint32_t)(arow0 & 7)) << 4;
    const int akh = (lane >> 4) & 1;
    const uint32_t aoff0 = (uint32_t)arow0 * 512;
    const uint32_t aoff1 = aoff0 + 16 * 512;
    const int brow = wn * 16 + ((lane >> 4) & 1) * 8 + (lane & 7);
    const uint32_t brx = ((uint32_t)(brow & 7)) << 4;
    const int bkh = (lane >> 3) & 1;
    const uint32_t boff = (uint32_t)brow * 512;

    const int v0  = blockIdx.x * 128;
    const int img = v0 >> 10;
    const int hw0 = v0 & 1023;

    float b1[4], b2[4], b3[4], nzr[4];
    int   i1[4], i2[4];
#pragma unroll
    for (int s = 0; s < 4; s++) {
        b1[s] = 3.4e38f; b2[s] = 3.4e38f; b3[s] = 3.4e38f; i1[s] = 0; i2[s] = 0;
        nzr[s] = g_nz[v0 + wm * 32 + (s >> 1) * 16 + (s & 1) * 8 + (lane >> 2)];
    }

    // ---- prologue: cp.async A tile (64KB, pre-split) + B chunk 0 ----
    {
        const char* aG = (const char*)g_Ah + (size_t)v0 * 512;
        for (int i = tid; i < 4096; i += 256)
            __pipeline_memcpy_async(smem + SA_H + i * 16, aG + i * 16, 16);
        const char* sH = (const char*)g_Bh;
        for (int i = tid; i < 1024; i += 256)
            __pipeline_memcpy_async(smem + SB + i * 16, sH + i * 16, 16);
        __pipeline_commit();
    }

    for (int nc = 0; nc < 32; nc++) {
        const int b = nc & 1;
        if (nc + 1 < 32) {
            const char* sH = (const char*)g_Bh + (size_t)(nc + 1) * 32 * 512;
            uint32_t db = (uint32_t)(SB + (1 - b) * 16384);
            for (int i = tid; i < 1024; i += 256)
                __pipeline_memcpy_async(smem + db + i * 16, sH + i * 16, 16);
            __pipeline_commit();
            __pipeline_wait_prior(1);
        } else {
            __pipeline_wait_prior(0);
        }
        __syncthreads();

        float acc[2][2][4];
#pragma unroll
        for (int mi = 0; mi < 2; mi++)
#pragma unroll
            for (int ni = 0; ni < 2; ni++)
#pragma unroll
                for (int c = 0; c < 4; c++) acc[mi][ni][c] = 0.f;

        const uint32_t bH = sb + SB + b * 16384 + boff;
        const uint32_t aH0 = sb + SA_H + aoff0, aH1 = sb + SA_H + aoff1;

#pragma unroll
        for (int ks = 0; ks < 16; ks++) {
            uint32_t akc = (((uint32_t)(ks * 2 + akh)) << 4) ^ arx;
            uint32_t bkc = (((uint32_t)(ks * 2 + bkh)) << 4) ^ brx;
            uint32_t ah0[4], ah1[4], bh[4];
            LDSM4(ah0, aH0 + akc);
            LDSM4(ah1, aH1 + akc);
            LDSM4(bh,  bH + bkc);
#pragma unroll
            for (int ni = 0; ni < 2; ni++) {
                MMA16816(acc[0][ni], ah0, bh[ni * 2], bh[ni * 2 + 1]);
                MMA16816(acc[1][ni], ah1, bh[ni * 2], bh[ni * 2 + 1]);
            }
        }

        // ---- fold into running top-3, reference rounding chain ----
#pragma unroll
        for (int mi = 0; mi < 2; mi++)
#pragma unroll
            for (int ch = 0; ch < 2; ch++) {
                int s = mi * 2 + ch;
#pragma unroll
                for (int ni = 0; ni < 2; ni++)
#pragma unroll
                    for (int cl = 0; cl < 2; cl++) {
                        int code  = nc * 32 + wn * 16 + ni * 8 + (lane & 3) * 2 + cl;
                        float dot = acc[mi][ni][ch * 2 + cl] * EINV;
                        float d   = fmaf(-2.0f, dot, nzr[s]) + nes[code];
                        if (d < b1[s]) {
                            b3[s] = b2[s]; b2[s] = b1[s]; i2[s] = i1[s];
                            b1[s] = d; i1[s] = code;
                        } else if (d < b2[s]) {
                            b3[s] = b2[s]; b2[s] = d; i2[s] = code;
                        } else if (d < b3[s]) {
                            b3[s] = d;
                        }
                    }
            }
        __syncthreads();
    }

    // ---- cross-lane merge (xor 1,2) of the top-3 triples ----
#pragma unroll
    for (int s = 0; s < 4; s++) {
#pragma unroll
        for (int off = 1; off <= 2; off <<= 1) {
            float ob1 = __shfl_xor_sync(0xffffffffu, b1[s], off);
            float ob2 = __shfl_xor_sync(0xffffffffu, b2[s], off);
            float ob3 = __shfl_xor_sync(0xffffffffu, b3[s], off);
            int   oi1 = __shfl_xor_sync(0xffffffffu, i1[s], off);
            int   oi2 = __shfl_xor_sync(0xffffffffu, i2[s], off);
            merge3c(b1[s], i1[s], b2[s], i2[s], b3[s], ob1, oi1, ob2, oi2, ob3);
        }
        if ((lane & 3) == 0) {
            int row = wm * 32 + (s >> 1) * 16 + (s & 1) * 8 + (lane >> 2);
            ((float*)(smem + SB1))[row * 2 + wn] = b1[s];
            ((float*)(smem + SB2))[row * 2 + wn] = b2[s];
            ((float*)(smem + SB3))[row * 2 + wn] = b3[s];
            ((int*)(smem + SI1))[row * 2 + wn]   = i1[s];
            ((int*)(smem + SI2))[row * 2 + wn]   = i2[s];
        }
    }
    __syncthreads();
    float myd = 0.f;
    if (tid < 128) {
        float a1 = ((float*)(smem + SB1))[tid * 2];
        float a2 = ((float*)(smem + SB2))[tid * 2];
        float a3 = ((float*)(smem + SB3))[tid * 2];
        int   x1 = ((int*)(smem + SI1))[tid * 2];
        int   x2 = ((int*)(smem + SI2))[tid * 2];
        merge3c(a1, x1, a2, x2, a3,
                ((float*)(smem + SB1))[tid * 2 + 1],
                ((int*)(smem + SI1))[tid * 2 + 1],
                ((float*)(smem + SB2))[tid * 2 + 1],
                ((int*)(smem + SI2))[tid * 2 + 1],
                ((float*)(smem + SB3))[tid * 2 + 1]);
        ((int*)(smem + SROW))[tid] = x1;
        int row = v0 + tid;
        g_code[row] = x1;
        myd = a1;                               // row loss = winning distance
        if (a3 - a1 <= WIN_ULP * ulpf(a3)) {
            int p = atomicAdd(&g_cntB, 1);
            if (p < FIXBCAP) g_fixB_row[p] = row;
        } else if (a2 - a1 <= WIN_ULP * ulpf(a2)) {
            int p = atomicAdd(&g_cntA, 1);
            if (p < FIXCAP) {
                g_fixA_row[p] = row; g_fixA_c1[p] = x1; g_fixA_c2[p] = x2;
            }
        }
    }
    // loss reduction (warps 0-3 carry data; 4-7 contribute 0)
    for (int o = 16; o > 0; o >>= 1) myd += __shfl_down_sync(0xffffffffu, myd, o);
    if (lane == 0) ((float*)(smem + SRED))[wid] = myd;
    __syncthreads();
    if (tid == 0) {
        float t = 0.f;
        for (int w = 0; w < 8; w++) t += ((float*)(smem + SRED))[w];
        atomicAdd(&g_loss, (double)t);
    }
    __syncthreads();

    // ---- gather: 2 threads per row, 128 channels each (E -> out only) ----
    {
        int row = tid & 127, chh = tid >> 7;
        int code = ((int*)(smem + SROW))[row];
        const float4* er = (const float4*)(E + (size_t)code * CDIM) + chh * 32;
        float* op = out + (size_t)img * CDIM * HW + (size_t)(chh * 128) * HW + hw0 + row;
#pragma unroll 4
        for (int q = 0; q < 32; q++) {
            float4 e4 = er[q];
            op[(size_t)(q * 4 + 0) * HW] = e4.x;
            op[(size_t)(q * 4 + 1) * HW] = e4.y;
            op[(size_t)(q * 4 + 2) * HW] = e4.z;
            op[(size_t)(q * 4 + 3) * HW] = e4.w;
        }
    }
}

// ======== fix A: exact 2-candidate compare, one warp per flagged row ========
__global__ void __launch_bounds__(128, 8)
vq_fixA(const float* __restrict__ Z, const float* __restrict__ E,
        float* __restrict__ out) {
    const int lane = threadIdx.x & 31;
    const int gw   = (blockIdx.x * blockDim.x + threadIdx.x) >> 5;
    const int nw   = (gridDim.x * blockDim.x) >> 5;
    int nf = g_cntA; if (nf > FIXCAP) nf = FIXCAP;

    for (int li = gw; li < nf; li += nw) {
        int r  = g_fixA_row[li];
        int c1 = g_fixA_c1[li], c2 = g_fixA_c2[li];
        int img = r >> 10, hw = r & 1023;
        const float* zp = Z + (size_t)img * (CDIM * HW) + hw;
        const float* e1 = E + (size_t)c1 * CDIM;
        const float* e2 = E + (size_t)c2 * CDIM;

        float p1 = 0.f, p2 = 0.f;
#pragma unroll
        for (int q = 0; q < 8; q++) {
            int k = lane * 8 + q;
            float zv = zp[(size_t)k * HW];
            p1 = fmaf(zv, e1[k], p1);
            p2 = fmaf(zv, e2[k], p2);
        }
#pragma unroll
        for (int o = 16; o > 0; o >>= 1) {
            p1 += __shfl_xor_sync(0xffffffffu, p1, o);
            p2 += __shfl_xor_sync(0xffffffffu, p2, o);
        }
        int win = 0; float delta = 0.f;
        if (lane == 0) {
            float nz = g_nz[r];
            float d1 = fmaf(-2.0f, p1, nz) + g_ne[c1];
            float d2 = fmaf(-2.0f, p2, nz) + g_ne[c2];
            if (d2 < d1 || (d2 == d1 && c2 < c1)) { win = c2; delta = d2 - d1; }
            else win = c1;
        }
        win = __shfl_sync(0xffffffffu, win, 0);
        if (win != c1) {
            const float* en = E + (size_t)win * CDIM;
#pragma unroll
            for (int q = 0; q < 8; q++) {
                int k = lane * 8 + q;
                out[(size_t)img * (CDIM * HW) + (size_t)k * HW + hw] = en[k];
            }
            if (lane == 0) {
                atomicAdd(&g_loss, (double)delta);
                g_code[r] = win;
            }
        }
    }
}

// ======== fix B: full 1024-code exact rescan, one block per rare row ========
__global__ void __launch_bounds__(256, 1)
vq_fixB(const float* __restrict__ Z, const float* __restrict__ E,
        float* __restrict__ out) {
    __shared__ float zs[CDIM];
    __shared__ float sd[256];
    __shared__ int   si[256];
    __shared__ float soldd;
    const int tid = threadIdx.x;
    int nb = g_cntB; if (nb > FIXBCAP) nb = FIXBCAP;

    for (int li = blockIdx.x; li < nb; li += gridDim.x) {
        int r = g_fixB_row[li];
        int img = r >> 10, hw = r & 1023;
        int oc = g_code[r];
        const float* zp = Z + (size_t)img * (CDIM * HW) + hw;
        __syncthreads();
        if (tid < 256) zs[tid] = zp[(size_t)tid * HW];
        __syncthreads();
        float nz = g_nz[r];

        float bd = 3.4e38f; int bi = 0;
#pragma unroll
        for (int q = 0; q < 4; q++) {
            int c = tid * 4 + q;
            const float4* ev = (const float4*)(E + (size_t)c * CDIM);
            const float4* z4 = (const float4*)zs;
            float dot = 0.f;
#pragma unroll 8
            for (int k4 = 0; k4 < 64; k4++) {
                float4 e4 = ev[k4], zq = z4[k4];
                dot = fmaf(zq.x, e4.x, dot);
                dot = fmaf(zq.y, e4.y, dot);
                dot = fmaf(zq.z, e4.z, dot);
                dot = fmaf(zq.w, e4.w, dot);
            }
            float d = fmaf(-2.0f, dot, nz) + g_ne[c];
            if (c == oc) soldd = d;
            if (d < bd) { bd = d; bi = c; }
        }
        sd[tid] = bd; si[tid] = bi;
        __syncthreads();
        for (int st = 128; st > 0; st >>= 1) {
            if (tid < st) {
                float od = sd[tid + st]; int oi = si[tid + st];
                if (od < sd[tid] || (od == sd[tid] && oi < si[tid])) {
                    sd[tid] = od; si[tid] = oi;
                }
            }
            __syncthreads();
        }
        int w = si[0];
        float dnew = sd[0];
        __syncthreads();
        if (w != oc) {
            const float* en = E + (size_t)w * CDIM;
            if (tid < 256)
                out[(size_t)img * (CDIM * HW) + (size_t)tid * HW + hw] = en[tid];
            if (tid == 0) {
                atomicAdd(&g_loss, (double)(dnew - soldd));
                g_code[r] = w;
            }
        }
        __syncthreads();
    }
}

// ======== finalize scalars ========
__global__ void vq_final(float* out, int out_size) {
    if (out_size >= QELEMS + 1) {
        float vq = (float)(g_loss / (double)QELEMS);
        out[QELEMS] = vq;
        if (out_size >= QELEMS + 2) out[QELEMS + 1] = 0.25f * vq;
    }
}

extern "C" void kernel_launch(void* const* d_in, const int* in_sizes, int n_in,
                              void* d_out, int out_size) {
    const float* Z = (const float*)d_in[0];
    const float* E = (const float*)d_in[1];
    if (n_in >= 2 && in_sizes[0] == KCODES * CDIM && in_sizes[1] == QELEMS) {
        const float* t = Z; Z = E; E = t;
    }
    float* out = (float*)d_out;

    cudaFuncSetAttribute(vq_main, cudaFuncAttributeMaxDynamicSharedMemorySize, SMEM_TOTAL);
    vq_prep_e<<<KCODES, 64>>>(E);
    vq_prep_z<<<NVEC / 128, 128>>>(Z);
    vq_main<<<NVEC / 128, 256, SMEM_TOTAL>>>(Z, E, out);
    vq_fixA<<<256, 128>>>(Z, E, out);
    vq_fixB<<<64, 256>>>(Z, E, out);
    vq_final<<<1, 1>>>(out, out_size);
}